// round 14
// baseline (speedup 1.0000x reference)
#include <cuda_runtime.h>
#include <cuda_fp16.h>
#include <cstdint>
#include <cstddef>

// ---------------------------------------------------------------------------
// Problem dims
// ---------------------------------------------------------------------------
static constexpr int N_IN  = 2048;
static constexpr int N_HID = 4096;
static constexpr int N_OUT = 1024;
static constexpr int N_TOT = 7168;
static constexpr int BATCH = 4096;
static constexpr int KA    = N_IN + N_HID;   // 6144 : packed A = [x | hidden]

// ---------------------------------------------------------------------------
// Device scratch (allocation-free rule: __device__ globals).
// All coordination state is MONOTONIC across kernel launches (graph replays):
//   g_bar  : barrier arrivals, +GRID_P per launch  -> generation = my/GRID_P
//   g_tk   : ticket claims,    +CLAIMS_PER_GEN per launch (exact)
//   g_cntm : per-rowblock done G1 tiles, +G1_COLS per launch
// ---------------------------------------------------------------------------
__device__ __align__(1024) __half g_A[(size_t)BATCH * KA];       // [x | hidden] fp16
__device__ __align__(1024) __half g_B1[(size_t)N_HID * N_IN];    // W1^T fp16
__device__ __align__(1024) __half g_B2[(size_t)N_OUT * KA];      // W2^T fp16
__device__ unsigned g_bar;
__device__ unsigned g_tk;
__device__ unsigned g_cntm[BATCH / 128];

#define DEVFN __device__ __forceinline__

DEVFN uint32_t smem_u32(const void* p) {
    uint32_t a;
    asm("{ .reg .u64 t; cvta.to.shared.u64 t, %1; cvt.u32.u64 %0, t; }"
        : "=r"(a) : "l"(p));
    return a;
}

DEVFN void cp16(uint32_t s, const void* g) {
    asm volatile("cp.async.cg.shared.global [%0], [%1], 16;"
                 :: "r"(s), "l"(g));
}
DEVFN void cp_commit() { asm volatile("cp.async.commit_group;"); }
template <int N> DEVFN void cp_wait() {
    asm volatile("cp.async.wait_group %0;" :: "n"(N));
}

DEVFN void ldsm4(uint32_t* r, uint32_t a) {
    asm volatile("ldmatrix.sync.aligned.m8n8.x4.shared.b16 {%0,%1,%2,%3}, [%4];"
                 : "=r"(r[0]), "=r"(r[1]), "=r"(r[2]), "=r"(r[3]) : "r"(a));
}

DEVFN void mma16816(float* d, const uint32_t* a, uint32_t b0, uint32_t b1) {
    asm volatile(
        "mma.sync.aligned.m16n8k16.row.col.f32.f16.f16.f32 "
        "{%0,%1,%2,%3}, {%4,%5,%6,%7}, {%8,%9}, {%0,%1,%2,%3};"
        : "+f"(d[0]), "+f"(d[1]), "+f"(d[2]), "+f"(d[3])
        : "r"(a[0]), "r"(a[1]), "r"(a[2]), "r"(a[3]), "r"(b0), "r"(b1));
}

DEVFN uint32_t pack2h(__half a, __half b) {
    return (uint32_t)__half_as_ushort(a) |
           ((uint32_t)__half_as_ushort(b) << 16);
}

DEVFN unsigned ldacq_u(const unsigned* p) {
    unsigned v;
    asm volatile("ld.global.acquire.gpu.b32 %0, [%1];" : "=r"(v) : "l"(p));
    return v;
}

// ---------------------------------------------------------------------------
// Geometry / scheduling constants
// ---------------------------------------------------------------------------
static constexpr int BM = 128, BN = 128, BK = 64;
static constexpr int STAGES  = 3;
static constexpr int TILE_B  = BM * BK * 2;        // 16 KB
static constexpr int STAGE_B = 2 * TILE_B;         // A + B = 32 KB
static constexpr int SMEM_GEMM = STAGES * STAGE_B + 128;   // ~96 KB

static constexpr int GRID_P   = 296;               // persistent CTAs (2/SM)
static constexpr int G1_TILES = (BATCH / BM) * (N_HID / BN);  // 1024
static constexpr int G2_TILES = (BATCH / BM) * (N_OUT / BN);  // 256
static constexpr int TOT_TILES = G1_TILES + G2_TILES;         // 1280
static constexpr unsigned CLAIMS_PER_GEN = TOT_TILES + GRID_P; // 1576 exact
static constexpr int G1_COLS  = N_HID / BN;                   // 32
static constexpr int KC1 = N_IN / BK;                         // 32
static constexpr int KC2 = KA / BK;                           // 96

// pack-phase geometry
static constexpr int NX_U2   = BATCH * (N_IN / 4);            // 2,097,152 uint2 units
static constexpr int W1_NB   = N_HID / 32, W1_KB = N_IN / 64; // 128, 32
static constexpr int W2_NB   = N_OUT / 32, W2_KB = KA / 64;   // 32, 96
static constexpr int PW1     = W1_NB * W1_KB;                 // 4096 tiles
static constexpr int PW2     = W2_NB * W2_KB;                 // 3072 tiles
static constexpr int PW_TOT  = PW1 + PW2;                     // 7168 tiles

// ---------------------------------------------------------------------------
// Persistent fused kernel: phase 0 packs (x->fp16 A, W1^T, W2^T), then a
// device-wide barrier (all GRID_P CTAs co-resident), then the ticketed
// GEMM1+GEMM2 with continuous cp.async ring (R13 structure, monotonic state).
// ---------------------------------------------------------------------------
__global__ __launch_bounds__(128, 2)
void net_gemm(float* __restrict__ out,
              const float4* __restrict__ x,
              const float* __restrict__ W)
{
    extern __shared__ char smraw[];
    uint32_t sb = (smem_u32(smraw) + 127u) & ~127u;
    __shared__ int sh_ticket;
    __shared__ unsigned sh_gen;

    const int tid  = threadIdx.x;
    const int wid  = tid >> 5;
    const int lane = tid & 31;
    const int bid  = blockIdx.x;

    // ======================= phase 0 : packing =======================
    // (a) x -> fp16 into g_A cols [0, N_IN)
    for (int idx = bid * 128 + tid; idx < NX_U2; idx += GRID_P * 128) {
        int m  = idx / (N_IN / 4);
        int k4 = idx % (N_IN / 4);
        float4 v = x[idx];
        uint2 u;
        u.x = pack2h(__float2half(v.x), __float2half(v.y));
        u.y = pack2h(__float2half(v.z), __float2half(v.w));
        *(uint2*)(g_A + (size_t)m * KA + k4 * 4) = u;
    }
    // (b) W transpose tiles (k64 x n32), 128 threads as (32, 4)
    {
        float (*t)[33] = (float (*)[33])smraw;
        const int tx = tid & 31, ty = tid >> 5;   // ty 0..3
        for (int tt = bid; tt < PW_TOT; tt += GRID_P) {
            int col0, pitchK, nb, kb;
            __half* outB;
            if (tt < PW1) {
                col0 = N_IN; pitchK = N_IN; outB = g_B1;
                nb = (tt % W1_NB) * 32; kb = (tt / W1_NB) * 64;
            } else {
                int b = tt - PW1;
                col0 = N_IN + N_HID; pitchK = KA; outB = g_B2;
                nb = (b % W2_NB) * 32; kb = (b / W2_NB) * 64;
            }
            #pragma unroll
            for (int i = 0; i < 16; i++) {
                int k = kb + ty + i * 4;
                t[ty + i * 4][tx] = W[(size_t)k * N_TOT + col0 + nb + tx];
            }
            __syncthreads();
            #pragma unroll
            for (int i = 0; i < 8; i++) {
                int n = nb + ty + i * 4;
                int k2 = tx * 2;
                uint32_t u = pack2h(__float2half(t[k2][ty + i * 4]),
                                    __float2half(t[k2 + 1][ty + i * 4]));
                *(uint32_t*)(outB + (size_t)n * pitchK + kb + k2) = u;
            }
            __syncthreads();
        }
    }

    // ================== device-wide barrier (monotonic) ==================
    __threadfence();
    __syncthreads();
    if (tid == 0) {
        unsigned my  = atomicAdd(&g_bar, 1u);
        unsigned gen = my / GRID_P;
        while (ldacq_u(&g_bar) < (gen + 1u) * GRID_P) __nanosleep(64);
        sh_gen = gen;
    }
    __syncthreads();
    const unsigned gen = sh_gen;
    const unsigned tk_base  = gen * CLAIMS_PER_GEN;
    const unsigned cnt_goal = gen * (unsigned)G1_COLS + (unsigned)G1_COLS;

    // ======================= phase 1 : fused GEMM =======================
    // loader thread offsets
    const int c16 = tid & 7;
    const int rbt = tid >> 3;         // base row 0..15
    const uint32_t srow0 =
        (uint32_t)rbt * 128 + (((uint32_t)c16 * 16) ^ (((uint32_t)rbt & 7) << 4));

    const __half* pA;
    const __half* pB;
    int  l_ldB, l_kc, l_rowblk, lc;
    bool l_g2;

    auto set_loader = [&](int t) {
        int m0, n0; const __half* Bb;
        if (t < G1_TILES) {
            l_g2 = false; l_rowblk = t >> 5;
            m0 = l_rowblk * BM; n0 = (t & 31) * BN;
            Bb = g_B1; l_ldB = N_IN; l_kc = KC1;
        } else {
            int u = t - G1_TILES;
            l_g2 = true; l_rowblk = u >> 3;
            m0 = l_rowblk * BM; n0 = (u & 7) * BN;
            Bb = g_B2; l_ldB = KA; l_kc = KC2;
        }
        pA = g_A + (size_t)(m0 + rbt) * KA + c16 * 8;
        pB = Bb + (size_t)(n0 + rbt) * l_ldB + c16 * 8;
        lc = 0;
    };

    auto claim = [&]() -> int {
        if (tid == 0) sh_ticket = (int)(atomicAdd(&g_tk, 1u) - tk_base);
        __syncthreads();
        return sh_ticket;
    };

    int  comp_id = claim();           // first tile (always valid: 1280 > 296)
    int  next_id = -1;
    bool have_load = true, pending_next = false;
    int  ls = 0, cs = 0;

    set_loader(comp_id);

    auto issue_load = [&]() {
        if (!have_load) return;
        if (l_g2 && lc == KC1) {
            if (tid == 0) {
                while (ldacq_u(&g_cntm[l_rowblk]) < cnt_goal) __nanosleep(128);
            }
            __syncthreads();
        }
        uint32_t st = sb + ls * STAGE_B;
        #pragma unroll
        for (int j = 0; j < 8; j++) {
            cp16(st + srow0 + (uint32_t)(16 * j) * 128,
                 pA + (size_t)(16 * j) * KA);
            cp16(st + TILE_B + srow0 + (uint32_t)(16 * j) * 128,
                 pB + (size_t)(16 * j) * l_ldB);
        }
        pA += BK; pB += BK;
        if (++ls == STAGES) ls = 0;
        if (++lc == l_kc) {
            int t = claim();
            if (t < TOT_TILES) { next_id = t; pending_next = true; set_loader(t); }
            else have_load = false;
        }
    };

    // fragment address precompute (manual swizzle)
    const int warp_m = wid >> 1;      // 0..1 : 64 rows
    const int warp_n = wid & 1;       // 0..1 : 64 cols
    const uint32_t aOff0 = (uint32_t)(warp_m * 64 + (lane & 15)) * 128;
    const uint32_t aKq   = ((uint32_t)lane >> 4) * 16;
    const uint32_t amask = ((uint32_t)lane & 7) << 4;
    const uint32_t bOff0 =
        (uint32_t)(warp_n * 64 + (lane & 7) + ((lane >> 4) << 3)) * 128;
    const uint32_t bKq   = (((uint32_t)lane >> 3) & 1) * 16;
    const uint32_t bmask = ((uint32_t)lane & 7) << 4;

    float acc[4][8][4];
    #pragma unroll
    for (int mt = 0; mt < 4; mt++)
        #pragma unroll
        for (int nt = 0; nt < 8; nt++)
            #pragma unroll
            for (int r = 0; r < 4; r++)
                acc[mt][nt][r] = 0.0f;

    const int gr  = lane >> 2;
    const int gc2 = (lane & 3) * 2;

    // prologue: 2 chunks in flight
    issue_load(); cp_commit();
    issue_load(); cp_commit();

    // persistent tile loop
    for (;;) {
        const int kc_c = (comp_id < G1_TILES) ? KC1 : KC2;

        for (int c = 0; c < kc_c; c++) {
            cp_wait<STAGES - 2>();
            __syncthreads();
            issue_load();
            cp_commit();

            uint32_t st = sb + cs * STAGE_B;
            #pragma unroll
            for (int ks = 0; ks < 4; ks++) {
                const uint32_t kb = (uint32_t)ks * 32;
                uint32_t ah[4][4], bf[4][4];
                #pragma unroll
                for (int ng = 0; ng < 4; ng++)
                    ldsm4(bf[ng], st + TILE_B + bOff0 + ng * 2048 + ((kb + bKq) ^ bmask));
                #pragma unroll
                for (int mt = 0; mt < 4; mt++)
                    ldsm4(ah[mt], st + aOff0 + mt * 2048 + ((kb + aKq) ^ amask));
                #pragma unroll
                for (int mt = 0; mt < 4; mt++)
                    #pragma unroll
                    for (int nt = 0; nt < 8; nt++) {
                        const int ng = nt >> 1, hf = nt & 1;
                        mma16816(acc[mt][nt], ah[mt],
                                 bf[ng][hf * 2], bf[ng][hf * 2 + 1]);
                    }
            }
            if (++cs == STAGES) cs = 0;
        }

        // epilogue for comp_id
        int m0, n0, rowblk; bool g1;
        if (comp_id < G1_TILES) {
            g1 = true; rowblk = comp_id >> 5;
            m0 = rowblk * BM; n0 = (comp_id & 31) * BN;
        } else {
            int u = comp_id - G1_TILES;
            g1 = false; rowblk = u >> 3;
            m0 = rowblk * BM; n0 = (u & 7) * BN;
        }
        #pragma unroll
        for (int mt = 0; mt < 4; mt++)
            #pragma unroll
            for (int nt = 0; nt < 8; nt++)
                #pragma unroll
                for (int hf = 0; hf < 2; hf++) {
                    int row = m0 + warp_m * 64 + mt * 16 + gr + hf * 8;
                    int col = n0 + warp_n * 64 + nt * 8 + gc2;
                    float v0 = acc[mt][nt][hf * 2];
                    float v1 = acc[mt][nt][hf * 2 + 1];
                    if (g1) {
                        v0 = fmaxf(v0, 0.0f);
                        v1 = fmaxf(v1, 0.0f);
                        size_t o = (size_t)row * KA + N_IN + col;
                        *(uint32_t*)(g_A + o) =
                            pack2h(__float2half(v0), __float2half(v1));
                    } else {
                        *(float2*)(out + (size_t)row * N_OUT + col) =
                            make_float2(v0, v1);
                    }
                    acc[mt][nt][hf * 2]     = 0.0f;
                    acc[mt][nt][hf * 2 + 1] = 0.0f;
                }
        if (g1) {
            __threadfence();
            __syncthreads();
            if (tid == 0) atomicAdd(&g_cntm[rowblk], 1u);
        }

        if (!pending_next) break;
        comp_id = next_id;
        pending_next = false;
    }
}

// ---------------------------------------------------------------------------
// Host side — single launch
// ---------------------------------------------------------------------------
extern "C" void kernel_launch(void* const* d_in, const int* in_sizes, int n_in,
                              void* d_out, int out_size)
{
    const float* x = (const float*)d_in[0];        // (4096, 2048)
    const float* W = (const float*)d_in[1];        // (7168, 7168)
    float* out = (float*)d_out;                    // (4096, 1024)

    cudaFuncSetAttribute(net_gemm,
        cudaFuncAttributeMaxDynamicSharedMemorySize, SMEM_GEMM);

    net_gemm<<<GRID_P, 128, SMEM_GEMM>>>(out, (const float4*)x, W);
}

// round 16
// speedup vs baseline: 1.0926x; 1.0926x over previous
#include <cuda_runtime.h>
#include <cuda_fp16.h>
#include <cstdint>
#include <cstddef>

// ---------------------------------------------------------------------------
// Problem dims
// ---------------------------------------------------------------------------
static constexpr int N_IN  = 2048;
static constexpr int N_HID = 4096;
static constexpr int N_OUT = 1024;
static constexpr int N_TOT = 7168;
static constexpr int BATCH = 4096;
static constexpr int KA    = N_IN + N_HID;   // 6144 : packed A = [x | hidden]

// ---------------------------------------------------------------------------
// Device scratch (allocation-free rule: __device__ globals)
// ---------------------------------------------------------------------------
__device__ __align__(1024) __half g_A[(size_t)BATCH * KA];       // [x | hidden] fp16
__device__ __align__(1024) __half g_B1[(size_t)N_HID * N_IN];    // W1^T fp16
__device__ __align__(1024) __half g_B2[(size_t)N_OUT * KA];      // W2^T fp16
__device__ int g_cnt[BATCH / 128];   // per 128-row block: # finished GEMM1 tiles
__device__ int g_ticket;             // global tile ticket

#define DEVFN __device__ __forceinline__

DEVFN uint32_t smem_u32(const void* p) {
    uint32_t a;
    asm("{ .reg .u64 t; cvta.to.shared.u64 t, %1; cvt.u32.u64 %0, t; }"
        : "=r"(a) : "l"(p));
    return a;
}

DEVFN void cp16(uint32_t s, const void* g) {
    asm volatile("cp.async.cg.shared.global [%0], [%1], 16;"
                 :: "r"(s), "l"(g));
}

DEVFN void mbar_init(uint32_t a, uint32_t cnt) {
    asm volatile("mbarrier.init.shared.b64 [%0], %1;" :: "r"(a), "r"(cnt) : "memory");
}
DEVFN void mbar_arrive(uint32_t a) {
    asm volatile("mbarrier.arrive.shared.b64 _, [%0];" :: "r"(a) : "memory");
}
// NOINC: does NOT bump the pending count at issue; pure arrive at completion.
DEVFN void cp_arrive_noinc(uint32_t a) {
    asm volatile("cp.async.mbarrier.arrive.noinc.shared.b64 [%0];"
                 :: "r"(a) : "memory");
}
DEVFN void mbar_wait(uint32_t a, uint32_t ph) {
    uint32_t done;
    asm volatile("{\n\t.reg .pred p;\n\t"
        "mbarrier.try_wait.parity.acquire.cta.shared::cta.b64 p, [%1], %2;\n\t"
        "selp.b32 %0, 1, 0, p;\n\t}"
        : "=r"(done) : "r"(a), "r"(ph) : "memory");
    if (!done) {
        asm volatile("{\n\t.reg .pred P1;\n\t"
            "WL%=:\n\t"
            "mbarrier.try_wait.parity.acquire.cta.shared::cta.b64 P1, [%0], %1, 0x989680;\n\t"
            "@P1 bra.uni WD%=;\n\t"
            "bra.uni WL%=;\n\t"
            "WD%=:\n\t}"
            :: "r"(a), "r"(ph) : "memory");
    }
}

DEVFN void ldsm4(uint32_t* r, uint32_t a) {
    asm volatile("ldmatrix.sync.aligned.m8n8.x4.shared.b16 {%0,%1,%2,%3}, [%4];"
                 : "=r"(r[0]), "=r"(r[1]), "=r"(r[2]), "=r"(r[3]) : "r"(a));
}

DEVFN void mma16816(float* d, const uint32_t* a, uint32_t b0, uint32_t b1) {
    asm volatile(
        "mma.sync.aligned.m16n8k16.row.col.f32.f16.f16.f32 "
        "{%0,%1,%2,%3}, {%4,%5,%6,%7}, {%8,%9}, {%0,%1,%2,%3};"
        : "+f"(d[0]), "+f"(d[1]), "+f"(d[2]), "+f"(d[3])
        : "r"(a[0]), "r"(a[1]), "r"(a[2]), "r"(a[3]), "r"(b0), "r"(b1));
}

DEVFN uint32_t pack2h(__half a, __half b) {
    return (uint32_t)__half_as_ushort(a) |
           ((uint32_t)__half_as_ushort(b) << 16);
}

DEVFN int ld_acq(const int* p) {
    int v;
    asm volatile("ld.global.acquire.gpu.b32 %0, [%1];" : "=r"(v) : "l"(p));
    return v;
}

// ---------------------------------------------------------------------------
// Fused packing kernel (x pack + W1^T + W2^T), one launch.  (R13 version)
// ---------------------------------------------------------------------------
static constexpr int PX_BLK  = (BATCH * (N_IN / 4)) / 256;            // 8192
static constexpr int W1_NB   = N_HID / 32, W1_KB = N_IN / 64;         // 128, 32
static constexpr int W2_NB   = N_OUT / 32, W2_KB = KA / 64;           // 32, 96
static constexpr int PW1_BLK = W1_NB * W1_KB;                         // 4096
static constexpr int PW2_BLK = W2_NB * W2_KB;                         // 3072

static constexpr int GRID_P = 296;   // persistent CTAs (2/SM x 148)

__global__ void pack_all(const float4* __restrict__ x,
                         const float* __restrict__ W) {
    __shared__ float t[64][33];
    const int bid = blockIdx.x;
    const int tid = threadIdx.x;

    if (bid < PX_BLK) {
        int idx = bid * 256 + tid;
        if (idx < BATCH / 128) g_cnt[idx] = 0;      // reset dependency counters
        if (idx == BATCH / 128) g_ticket = GRID_P;  // first GRID_P tickets implicit
        int m  = idx / (N_IN / 4);
        int k4 = idx % (N_IN / 4);
        float4 v = x[idx];
        uint2 u;
        u.x = pack2h(__float2half(v.x), __float2half(v.y));
        u.y = pack2h(__float2half(v.z), __float2half(v.w));
        *(uint2*)(g_A + (size_t)m * KA + k4 * 4) = u;
        return;
    }

    int col0, pitchK, nb, kb;
    __half* outB;
    if (bid < PX_BLK + PW1_BLK) {
        int b = bid - PX_BLK;
        col0 = N_IN; pitchK = N_IN; outB = g_B1;
        nb = (b % W1_NB) * 32; kb = (b / W1_NB) * 64;
    } else {
        int b = bid - PX_BLK - PW1_BLK;
        col0 = N_IN + N_HID; pitchK = KA; outB = g_B2;
        nb = (b % W2_NB) * 32; kb = (b / W2_NB) * 64;
    }
    int tx = tid & 31, ty = tid >> 5;   // (32, 8)
    #pragma unroll
    for (int i = 0; i < 8; i++) {
        int k = kb + ty + i * 8;
        t[ty + i * 8][tx] = W[(size_t)k * N_TOT + col0 + nb + tx];
    }
    __syncthreads();
    #pragma unroll
    for (int i = 0; i < 4; i++) {
        int n = nb + ty + i * 8;
        int k2 = tx * 2;
        uint32_t u = pack2h(__float2half(t[k2][ty + i * 8]),
                            __float2half(t[k2 + 1][ty + i * 8]));
        *(uint32_t*)(outB + (size_t)n * pitchK + kb + k2) = u;
    }
}

// ---------------------------------------------------------------------------
// Persistent fused GEMM (R13 structure) with mbarrier chunk handoff:
//   full[s]  : count 128, armed per-thread via cp.async.mbarrier.arrive.NOINC
//   empty[s] : count 4,   lane0-per-warp arrive after the warp's LDSMs
// No per-chunk __syncthreads: warps overlap raggedly (~1 chunk drift bound).
// __syncthreads only at tile boundaries (ticket claim, G1 release).
// ---------------------------------------------------------------------------
static constexpr int BM = 128, BN = 128, BK = 64;
static constexpr int STAGES  = 3;
static constexpr int TILE_B  = BM * BK * 2;        // 16 KB
static constexpr int STAGE_B = 2 * TILE_B;         // A + B = 32 KB
static constexpr int SMEM_GEMM = STAGES * STAGE_B + 128;   // ~96 KB dynamic

static constexpr int G1_TILES = (BATCH / BM) * (N_HID / BN);  // 1024
static constexpr int G2_TILES = (BATCH / BM) * (N_OUT / BN);  // 256
static constexpr int TOT_TILES = G1_TILES + G2_TILES;         // 1280
static constexpr int G1_COLS  = N_HID / BN;                   // 32
static constexpr int KC1 = N_IN / BK;                         // 32
static constexpr int KC2 = KA / BK;                           // 96

__global__ __launch_bounds__(128, 2)
void net_gemm(float* __restrict__ out)
{
    extern __shared__ char smraw[];
    uint32_t sb = (smem_u32(smraw) + 127u) & ~127u;
    __shared__ __align__(8) unsigned long long mb_full[STAGES];
    __shared__ __align__(8) unsigned long long mb_empty[STAGES];
    __shared__ int sh_ticket;

    const int tid  = threadIdx.x;
    const int wid  = tid >> 5;
    const int lane = tid & 31;
    const int bid  = blockIdx.x;

    const uint32_t mbF = smem_u32(mb_full);
    const uint32_t mbE = smem_u32(mb_empty);

    if (tid == 0) {
        #pragma unroll
        for (int s = 0; s < STAGES; s++) {
            mbar_init(mbF + s * 8, 128);   // 128 noinc cp-arrives per phase
            mbar_init(mbE + s * 8, 4);     // one arrive per warp
        }
    }
    __syncthreads();

    // ---- loader thread offsets ----
    const int c16 = tid & 7;          // 16B unit within 128B row
    const int rbt = tid >> 3;         // base row (0..15)
    const uint32_t srow0 =
        (uint32_t)rbt * 128 + (((uint32_t)c16 * 16) ^ (((uint32_t)rbt & 7) << 4));

    // ---- loader state ----
    const __half* pA;
    const __half* pB;
    int  l_ldB, l_kc, l_rowblk, lc;
    bool l_g2;

    auto set_loader = [&](int t) {
        int m0, n0; const __half* Bb;
        if (t < G1_TILES) {
            l_g2 = false; l_rowblk = t >> 5;
            m0 = l_rowblk * BM; n0 = (t & 31) * BN;
            Bb = g_B1; l_ldB = N_IN; l_kc = KC1;
        } else {
            int u = t - G1_TILES;
            l_g2 = true; l_rowblk = u >> 3;
            m0 = l_rowblk * BM; n0 = (u & 7) * BN;
            Bb = g_B2; l_ldB = KA; l_kc = KC2;
        }
        pA = g_A + (size_t)(m0 + rbt) * KA + c16 * 8;
        pB = Bb + (size_t)(n0 + rbt) * l_ldB + c16 * 8;
        lc = 0;
    };

    int  comp_id = bid;             // first ticket implicit (g_ticket = GRID_P)
    int  next_id = -1;
    bool have_load = true, pending_next = false;
    int  ls = 0, cs = 0;
    int  n_load = 0;                // total chunks issued (global stream)
    uint32_t fpm = 0, epm = 0;      // per-slot parity bitmasks

    set_loader(comp_id);

    auto issue_load = [&]() {
        if (!have_load) return;
        if (l_g2 && lc == KC1) {
            // first hidden-dependent chunk: all threads spin (no CTA sync)
            while (ld_acq(&g_cnt[l_rowblk]) < G1_COLS) __nanosleep(128);
        }
        if (n_load >= STAGES) {     // slot reuse: wait consumers released it
            mbar_wait(mbE + ls * 8, (epm >> ls) & 1u);
            epm ^= 1u << ls;
        }
        uint32_t st = sb + ls * STAGE_B;
        #pragma unroll
        for (int j = 0; j < 8; j++) {
            cp16(st + srow0 + (uint32_t)(16 * j) * 128,
                 pA + (size_t)(16 * j) * KA);
            cp16(st + TILE_B + srow0 + (uint32_t)(16 * j) * 128,
                 pB + (size_t)(16 * j) * l_ldB);
        }
        cp_arrive_noinc(mbF + ls * 8);  // arrives when THIS thread's copies land
        n_load++;
        pA += BK; pB += BK;
        if (++ls == STAGES) ls = 0;
        if (++lc == l_kc) {
            __syncthreads();        // tile boundary: converge for uniform claim
            if (tid == 0) sh_ticket = atomicAdd(&g_ticket, 1);
            __syncthreads();
            int t = sh_ticket;
            if (t < TOT_TILES) { next_id = t; pending_next = true; set_loader(t); }
            else have_load = false;
        }
    };

    // ---- fragment address precompute (manual swizzle) ----
    const int warp_m = wid >> 1;      // 0..1 : 64 rows
    const int warp_n = wid & 1;       // 0..1 : 64 cols
    const uint32_t aOff0 = (uint32_t)(warp_m * 64 + (lane & 15)) * 128;
    const uint32_t aKq   = ((uint32_t)lane >> 4) * 16;
    const uint32_t amask = ((uint32_t)lane & 7) << 4;
    const uint32_t bOff0 =
        (uint32_t)(warp_n * 64 + (lane & 7) + ((lane >> 4) << 3)) * 128;
    const uint32_t bKq   = (((uint32_t)lane >> 3) & 1) * 16;
    const uint32_t bmask = ((uint32_t)lane & 7) << 4;

    float acc[4][8][4];
    #pragma unroll
    for (int mt = 0; mt < 4; mt++)
        #pragma unroll
        for (int nt = 0; nt < 8; nt++)
            #pragma unroll
            for (int r = 0; r < 4; r++)
                acc[mt][nt][r] = 0.0f;

    const int gr  = lane >> 2;
    const int gc2 = (lane & 3) * 2;

    // ---- prologue: 2 chunks in flight ----
    issue_load();
    issue_load();

    // ---- persistent tile loop ----
    for (;;) {
        const int kc_c = (comp_id < G1_TILES) ? KC1 : KC2;

        for (int c = 0; c < kc_c; c++) {
            // wait chunk resident (acquire orders cp.async data for ldsm)
            mbar_wait(mbF + cs * 8, (fpm >> cs) & 1u);
            fpm ^= 1u << cs;

            uint32_t st = sb + cs * STAGE_B;
            #pragma unroll
            for (int ks = 0; ks < 4; ks++) {
                const uint32_t kb = (uint32_t)ks * 32;
                uint32_t ah[4][4], bf[4][4];
                #pragma unroll
                for (int ng = 0; ng < 4; ng++)
                    ldsm4(bf[ng], st + TILE_B + bOff0 + ng * 2048 + ((kb + bKq) ^ bmask));
                #pragma unroll
                for (int mt = 0; mt < 4; mt++)
                    ldsm4(ah[mt], st + aOff0 + mt * 2048 + ((kb + aKq) ^ amask));
                #pragma unroll
                for (int mt = 0; mt < 4; mt++)
                    #pragma unroll
                    for (int nt = 0; nt < 8; nt++) {
                        const int ng = nt >> 1, hf = nt & 1;
                        mma16816(acc[mt][nt], ah[mt],
                                 bf[ng][hf * 2], bf[ng][hf * 2 + 1]);
                    }
            }
            __syncwarp();
            if (lane == 0) mbar_arrive(mbE + cs * 8);   // warp done with slot
            if (++cs == STAGES) cs = 0;

            issue_load();           // global stream, may cross tile boundary
        }

        // ---- epilogue for comp_id ----
        int m0, n0, rowblk; bool g1;
        if (comp_id < G1_TILES) {
            g1 = true; rowblk = comp_id >> 5;
            m0 = rowblk * BM; n0 = (comp_id & 31) * BN;
        } else {
            int u = comp_id - G1_TILES;
            g1 = false; rowblk = u >> 3;
            m0 = rowblk * BM; n0 = (u & 7) * BN;
        }
        #pragma unroll
        for (int mt = 0; mt < 4; mt++)
            #pragma unroll
            for (int nt = 0; nt < 8; nt++)
                #pragma unroll
                for (int hf = 0; hf < 2; hf++) {
                    int row = m0 + warp_m * 64 + mt * 16 + gr + hf * 8;
                    int col = n0 + warp_n * 64 + nt * 8 + gc2;
                    float v0 = acc[mt][nt][hf * 2];
                    float v1 = acc[mt][nt][hf * 2 + 1];
                    if (g1) {
                        v0 = fmaxf(v0, 0.0f);
                        v1 = fmaxf(v1, 0.0f);
                        size_t o = (size_t)row * KA + N_IN + col;
                        *(uint32_t*)(g_A + o) =
                            pack2h(__float2half(v0), __float2half(v1));
                    } else {
                        *(float2*)(out + (size_t)row * N_OUT + col) =
                            make_float2(v0, v1);
                    }
                    acc[mt][nt][hf * 2]     = 0.0f;
                    acc[mt][nt][hf * 2 + 1] = 0.0f;
                }
        if (g1) {
            __threadfence();          // order g_A stores
            __syncthreads();
            if (tid == 0) atomicAdd(&g_cnt[rowblk], 1);
        }

        if (!pending_next) break;
        comp_id = next_id;
        pending_next = false;
    }
}

// ---------------------------------------------------------------------------
// Host side
// ---------------------------------------------------------------------------
extern "C" void kernel_launch(void* const* d_in, const int* in_sizes, int n_in,
                              void* d_out, int out_size)
{
    const float* x = (const float*)d_in[0];        // (4096, 2048)
    const float* W = (const float*)d_in[1];        // (7168, 7168)
    float* out = (float*)d_out;                    // (4096, 1024)

    cudaFuncSetAttribute(net_gemm,
        cudaFuncAttributeMaxDynamicSharedMemorySize, SMEM_GEMM);

    // 1) fused packing: x -> g_A, W1^T -> g_B1, W2^T -> g_B2, counters+ticket
    pack_all<<<PX_BLK + PW1_BLK + PW2_BLK, 256>>>((const float4*)x, W);

    // 2) persistent fused GEMM1 + GEMM2 (mbarrier chunk handoff, noinc arrives)
    net_gemm<<<GRID_P, 128, SMEM_GEMM>>>(out);
}